// round 15
// baseline (speedup 1.0000x reference)
#include <cuda_runtime.h>
#include <cstdint>
#include <cmath>

#define Nn    768
#define CSd   384
#define NPROJ 1152
#define DOUT  2112
#define INFV  100000.0f

__device__ float g_proj [Nn * NPROJ];
__device__ float g_wcat [NPROJ * CSd];
__device__ float g_bcat [NPROJ];
__device__ float g_kh  [12 * Nn * 16];
__device__ float g_vh  [12 * Nn * 16];
__device__ float g_kph [12 * Nn * 12];
__device__ float g_vph [12 * Nn * 24];
__device__ float g_qpts[Nn * 144];
__device__ float g_bias[(size_t)12 * Nn * Nn];
__device__ float g_a   [(size_t)12 * Nn * Nn];
__device__ float g_cat [Nn * DOUT];
__device__ float g_part[3 * Nn * CSd];

__device__ __forceinline__ void ffma2(unsigned long long& d,
                                      unsigned long long a,
                                      unsigned long long b) {
    asm("fma.rn.f32x2 %0, %1, %2, %0;" : "+l"(d) : "l"(a), "l"(b));
}
__device__ __forceinline__ void addf2(unsigned long long& d, unsigned long long a) {
    asm("add.rn.f32x2 %0, %0, %1;" : "+l"(d) : "l"(a));
}
union F2U { unsigned long long u; float2 f; };

__device__ __forceinline__ uint32_t smaddr(const void* p) {
    return (uint32_t)__cvta_generic_to_shared(p);
}
__device__ __forceinline__ void cp16(uint32_t dst, const void* src) {
    asm volatile("cp.async.cg.shared.global [%0], [%1], 16;" :: "r"(dst), "l"(src));
}
__device__ __forceinline__ void cp_commit() {
    asm volatile("cp.async.commit_group;");
}
template<int N> __device__ __forceinline__ void cp_wait() {
    asm volatile("cp.async.wait_group %0;" :: "n"(N));
}

// ================= bias GEMM body (persistent i, cp.async double-buffer) ========
// smem floats: zb[2][8192] | swb 1536 | sbb 16 | part 6144  = 24080
#define SMA_BYTES (24080 * 4)
__device__ void bias_body(int i, const float* __restrict__ z,
                          const float* __restrict__ w_b, const float* __restrict__ b_b) {
    extern __shared__ float sm[];
    float* swb  = sm + 16384;
    float* sbb  = sm + 17920;
    float* part = sm + 17936;   // [8 cg][12 h][64 j]

    const int t = threadIdx.x;
    const int cg = t >> 5, jl = t & 31;

    for (int idx = t; idx < 384; idx += 256)
        ((float4*)swb)[idx] = ((const float4*)w_b)[idx];
    if (t < 12) sbb[t] = b_b[t];

    const float4* zbase = (const float4*)z + (size_t)i * Nn * 32;

    #pragma unroll
    for (int p = 0; p < 2; p++) {
        float* buf = sm + p * 8192;
        const float4* src = zbase + (size_t)p * 64 * 32;
        #pragma unroll
        for (int k = 0; k < 8; k++) {
            int idx = t + k * 256;
            int jj = idx >> 5, c4 = idx & 31;
            cp16(smaddr(buf + (size_t)(jj * 32 + (c4 ^ (jj & 31))) * 4),
                 src + (size_t)jj * 32 + c4);
        }
        cp_commit();
    }

    for (int tt = 0; tt < 12; tt++) {
        if (tt < 11) cp_wait<1>(); else cp_wait<0>();
        __syncthreads();

        const float* zr = sm + (tt & 1) * 8192;
        ulonglong2 zz[2][4];
        #pragma unroll
        for (int e = 0; e < 2; e++) {
            const float* rp = zr + (jl + 32 * e) * 128;
            #pragma unroll
            for (int cc = 0; cc < 4; cc++) {
                int c4 = cg * 4 + cc;
                zz[e][cc] = *(const ulonglong2*)(rp + ((c4 ^ jl) << 2));
            }
        }
        unsigned long long acc[12][2] = {};
        #pragma unroll
        for (int h = 0; h < 12; h++) {
            #pragma unroll
            for (int cc = 0; cc < 4; cc++) {
                int c4 = cg * 4 + cc;
                ulonglong2 ww = *(const ulonglong2*)(swb + h * 128 + (c4 << 2));
                ffma2(acc[h][0], zz[0][cc].x, ww.x);
                ffma2(acc[h][0], zz[0][cc].y, ww.y);
                ffma2(acc[h][1], zz[1][cc].x, ww.x);
                ffma2(acc[h][1], zz[1][cc].y, ww.y);
            }
        }
        #pragma unroll
        for (int h = 0; h < 12; h++) {
            F2U u0; u0.u = acc[h][0];
            F2U u1; u1.u = acc[h][1];
            part[(cg * 12 + h) * 64 + jl]      = u0.f.x + u0.f.y;
            part[(cg * 12 + h) * 64 + jl + 32] = u1.f.x + u1.f.y;
        }
        __syncthreads();

        if (tt + 2 < 12) {
            float* buf = sm + (tt & 1) * 8192;
            const float4* src = zbase + (size_t)(tt + 2) * 64 * 32;
            #pragma unroll
            for (int k = 0; k < 8; k++) {
                int idx = t + k * 256;
                int jj = idx >> 5, c4 = idx & 31;
                cp16(smaddr(buf + (size_t)(jj * 32 + (c4 ^ (jj & 31))) * 4),
                     src + (size_t)jj * 32 + c4);
            }
            cp_commit();
        }

        #pragma unroll
        for (int r = t; r < 768; r += 256) {
            int h = r >> 6, j = r & 63;
            float s2 = 0.f;
            #pragma unroll
            for (int c = 0; c < 8; c++) s2 += part[(c * 12 + h) * 64 + j];
            g_bias[((size_t)h * Nn + i) * Nn + tt * 64 + j] =
                0.5773502691896258f * (s2 + sbb[h]);
        }
    }
}

// ================= partner bodies ============================================
__device__ void copy_body(int bid, const float* __restrict__ wq, const float* __restrict__ bq,
                          const float* __restrict__ wkv, const float* __restrict__ bkv,
                          const float* __restrict__ wqp, const float* __restrict__ bqp,
                          const float* __restrict__ wkvp,const float* __restrict__ bkvp) {
    int idx = bid * 256 + threadIdx.x;
    if (idx < NPROJ * CSd) {
        int r = idx / CSd, k = idx - r * CSd;
        float v;
        if      (r < 192) v = wq  [ r        * CSd + k];
        else if (r < 576) v = wkv [(r - 192) * CSd + k];
        else if (r < 720) v = wqp [(r - 576) * CSd + k];
        else              v = wkvp[(r - 720) * CSd + k];
        g_wcat[idx] = v;
    }
    if (idx < NPROJ) {
        int r = idx;
        g_bcat[r] = (r < 192) ? bq[r] : (r < 576) ? bkv[r-192]
                  : (r < 720) ? bqp[r-576] : bkvp[r-720];
    }
}

__device__ void gemm_proj_body(int bid, const float* __restrict__ A) {
    constexpr int KK = CSd;
    constexpr int NC = NPROJ;
    const float* B    = g_wcat;
    const float* bias = g_bcat;
    float*       C    = g_proj;

    __shared__ float As[64][17];
    __shared__ float Bs[64][17];
    int t  = threadIdx.x;
    int m0 = (bid / 18) * 64, n0 = (bid % 18) * 64;
    int lr = t >> 2, lc = (t & 3) * 4;
    int ty = (t >> 4) * 4, tx = (t & 15) * 4;
    float acc[4][4] = {};

    for (int k0 = 0; k0 < KK; k0 += 16) {
        __syncthreads();
        float4 a4 = *(const float4*)(A + (size_t)(m0 + lr) * KK + k0 + lc);
        float4 b4 = *(const float4*)(B + (size_t)(n0 + lr) * KK + k0 + lc);
        As[lr][lc] = a4.x; As[lr][lc+1] = a4.y; As[lr][lc+2] = a4.z; As[lr][lc+3] = a4.w;
        Bs[lr][lc] = b4.x; Bs[lr][lc+1] = b4.y; Bs[lr][lc+2] = b4.z; Bs[lr][lc+3] = b4.w;
        __syncthreads();
        #pragma unroll
        for (int kk = 0; kk < 16; kk++) {
            float av[4], bv[4];
            #pragma unroll
            for (int r = 0; r < 4; r++) av[r] = As[ty + r][kk];
            #pragma unroll
            for (int c = 0; c < 4; c++) bv[c] = Bs[tx + c][kk];
            #pragma unroll
            for (int r = 0; r < 4; r++)
                #pragma unroll
                for (int c = 0; c < 4; c++)
                    acc[r][c] = fmaf(av[r], bv[c], acc[r][c]);
        }
    }
    #pragma unroll
    for (int r = 0; r < 4; r++)
        #pragma unroll
        for (int c = 0; c < 4; c++)
            C[(size_t)(m0 + ty + r) * NC + n0 + tx + c] = acc[r][c] + bias[n0 + tx + c];
}

__device__ void prep_body(int n, const float* __restrict__ rot, const float* __restrict__ trans) {
    const float* pr = g_proj + (size_t)n * NPROJ;
    float R[9];
    #pragma unroll
    for (int e = 0; e < 9; e++) R[e] = rot[n * 9 + e];
    float tr[3] = {trans[n*3+0], trans[n*3+1], trans[n*3+2]};

    for (int t = threadIdx.x; t < 960; t += 256) {
        if (t < 384) {
            int h = t >> 5, c = t & 31;
            float v = pr[192 + h * 32 + c];
            if (c < 16) g_kh[((size_t)h * Nn + n) * 16 + c]        = v;
            else        g_vh[((size_t)h * Nn + n) * 16 + (c - 16)] = v;
        } else if (t < 528) {
            int e = t - 384;
            int g = e / 3, ax = e - g * 3;
            const float* src = pr + 576 + g * 3;
            g_qpts[n * 144 + e] =
                R[ax*3+0]*src[0] + R[ax*3+1]*src[1] + R[ax*3+2]*src[2] + tr[ax];
        } else {
            int e2 = t - 528;
            int g = e2 / 3, ax = e2 - g * 3;
            const float* src = pr + 720 + g * 3;
            float val = R[ax*3+0]*src[0] + R[ax*3+1]*src[1] + R[ax*3+2]*src[2] + tr[ax];
            int h = g / 12, pp = g - h * 12;
            if (pp < 4) g_kph[((size_t)h * Nn + n) * 12 + pp * 3 + ax]       = val;
            else        g_vph[((size_t)h * Nn + n) * 24 + (pp - 4) * 3 + ax] = val;
        }
    }
}

// ================= fused phase-A launches =====================================
__global__ __launch_bounds__(256) void fusedA1(
    const float* __restrict__ z, const float* __restrict__ w_b, const float* __restrict__ b_b,
    const float* __restrict__ wq, const float* __restrict__ bq,
    const float* __restrict__ wkv, const float* __restrict__ bkv,
    const float* __restrict__ wqp, const float* __restrict__ bqp,
    const float* __restrict__ wkvp, const float* __restrict__ bkvp) {
    if (blockIdx.x < 256) bias_body(blockIdx.x, z, w_b, b_b);
    else copy_body(blockIdx.x - 256, wq, bq, wkv, bkv, wqp, bqp, wkvp, bkvp);
}

__global__ __launch_bounds__(256) void fusedA2(
    const float* __restrict__ z, const float* __restrict__ w_b, const float* __restrict__ b_b,
    const float* __restrict__ s) {
    if (blockIdx.x < 256) bias_body(blockIdx.x + 256, z, w_b, b_b);
    else gemm_proj_body(blockIdx.x - 256, s);
}

__global__ __launch_bounds__(256) void fusedA3(
    const float* __restrict__ z, const float* __restrict__ w_b, const float* __restrict__ b_b,
    const float* __restrict__ rot, const float* __restrict__ trans) {
    if (blockIdx.x < 256) bias_body(blockIdx.x + 512, z, w_b, b_b);
    else prep_body(blockIdx.x - 256, rot, trans);
}

// ---------------- output GEMM, K split 3 ----------------
__global__ void gemm_out_split(const float* __restrict__ w_out) {
    constexpr int KCH = DOUT / 3;    // 704
    const float* A = g_cat;
    const float* B = w_out;
    int kc = blockIdx.z;
    float* C = g_part + (size_t)kc * Nn * CSd;

    __shared__ float As[64][17];
    __shared__ float Bs[64][17];
    int t  = threadIdx.x;
    int m0 = blockIdx.y * 64, n0 = blockIdx.x * 64;
    int lr = t >> 2, lc = (t & 3) * 4;
    int ty = (t >> 4) * 4, tx = (t & 15) * 4;
    float acc[4][4] = {};

    for (int k0 = kc * KCH; k0 < (kc + 1) * KCH; k0 += 16) {
        __syncthreads();
        float4 a4 = *(const float4*)(A + (size_t)(m0 + lr) * DOUT + k0 + lc);
        float4 b4 = *(const float4*)(B + (size_t)(n0 + lr) * DOUT + k0 + lc);
        As[lr][lc] = a4.x; As[lr][lc+1] = a4.y; As[lr][lc+2] = a4.z; As[lr][lc+3] = a4.w;
        Bs[lr][lc] = b4.x; Bs[lr][lc+1] = b4.y; Bs[lr][lc+2] = b4.z; Bs[lr][lc+3] = b4.w;
        __syncthreads();
        #pragma unroll
        for (int kk = 0; kk < 16; kk++) {
            float av[4], bv[4];
            #pragma unroll
            for (int r = 0; r < 4; r++) av[r] = As[ty + r][kk];
            #pragma unroll
            for (int c = 0; c < 4; c++) bv[c] = Bs[tx + c][kk];
            #pragma unroll
            for (int r = 0; r < 4; r++)
                #pragma unroll
                for (int c = 0; c < 4; c++)
                    acc[r][c] = fmaf(av[r], bv[c], acc[r][c]);
        }
    }
    #pragma unroll
    for (int r = 0; r < 4; r++)
        #pragma unroll
        for (int c = 0; c < 4; c++)
            C[(size_t)(m0 + ty + r) * CSd + n0 + tx + c] = acc[r][c];
}

__global__ void gemm_out_combine(const float* __restrict__ b_out, float* __restrict__ out) {
    int idx = blockIdx.x * 256 + threadIdx.x;
    if (idx < Nn * CSd) {
        int c = idx % CSd;
        out[idx] = g_part[idx] + g_part[idx + Nn * CSd] + g_part[idx + 2 * Nn * CSd]
                 + b_out[c];
    }
}

// ---------------- KB: fused logits + softmax; warp = h, 2 i's per CTA ----------
#define SMB_BYTES (12 * 2 * 768 * 4)
__global__ __launch_bounds__(384) void attn_logits2(const float* __restrict__ mask,
                                                    const float* __restrict__ hwraw) {
    extern __shared__ float srows[];
    int i0 = blockIdx.x * 2;
    int h = threadIdx.x >> 5, lane = threadIdx.x & 31;
    float* row0 = srows + (h * 2 + 0) * 768;
    float* row1 = srows + (h * 2 + 1) * 768;

    float q[2][16], qp[2][12];
    #pragma unroll
    for (int ii = 0; ii < 2; ii++) {
        const float4* qs = (const float4*)(g_proj + (size_t)(i0+ii) * NPROJ + h * 16);
        #pragma unroll
        for (int c = 0; c < 4; c++) {
            float4 v = qs[c];
            q[ii][c*4+0] = v.x; q[ii][c*4+1] = v.y; q[ii][c*4+2] = v.z; q[ii][c*4+3] = v.w;
        }
        const float4* ps = (const float4*)(g_qpts + (size_t)(i0+ii) * 144 + h * 12);
        #pragma unroll
        for (int c = 0; c < 3; c++) {
            float4 v = ps[c];
            qp[ii][c*4+0] = v.x; qp[ii][c*4+1] = v.y; qp[ii][c*4+2] = v.z; qp[ii][c*4+3] = v.w;
        }
    }
    float x = hwraw[h];
    float hwv = ((x > 20.f) ? x : log1pf(expf(x))) * 0.13608276348795434f;
    float mi0 = mask[i0], mi1 = mask[i0 + 1];
    const float s1 = 0.14433756729740643f;
    float mx0 = -3.4e38f, mx1 = -3.4e38f;

    for (int j0 = 0; j0 < Nn; j0 += 32) {
        int j = j0 + lane;
        float mj = mask[j];
        const float4* kb = (const float4*)(g_kh + ((size_t)h * Nn + j) * 16);
        float4 k0 = kb[0], k1 = kb[1], k2 = kb[2], k3 = kb[3];
        const float4* pb = (const float4*)(g_kph + ((size_t)h * Nn + j) * 12);
        float4 p0 = pb[0], p1 = pb[1], p2 = pb[2];

        #pragma unroll
        for (int ii = 0; ii < 2; ii++) {
            float qk = 0.f;
            qk = fmaf(q[ii][0],  k0.x, qk); qk = fmaf(q[ii][1],  k0.y, qk);
            qk = fmaf(q[ii][2],  k0.z, qk); qk = fmaf(q[ii][3],  k0.w, qk);
            qk = fmaf(q[ii][4],  k1.x, qk); qk = fmaf(q[ii][5],  k1.y, qk);
            qk = fmaf(q[ii][6],  k1.z, qk); qk = fmaf(q[ii][7],  k1.w, qk);
            qk = fmaf(q[ii][8],  k2.x, qk); qk = fmaf(q[ii][9],  k2.y, qk);
            qk = fmaf(q[ii][10], k2.z, qk); qk = fmaf(q[ii][11], k2.w, qk);
            qk = fmaf(q[ii][12], k3.x, qk); qk = fmaf(q[ii][13], k3.y, qk);
            qk = fmaf(q[ii][14], k3.z, qk); qk = fmaf(q[ii][15], k3.w, qk);

            float d2 = 0.f, d;
            d = qp[ii][0]  - p0.x; d2 = fmaf(d, d, d2);
            d = qp[ii][1]  - p0.y; d2 = fmaf(d, d, d2);
            d = qp[ii][2]  - p0.z; d2 = fmaf(d, d, d2);
            d = qp[ii][3]  - p0.w; d2 = fmaf(d, d, d2);
            d = qp[ii][4]  - p1.x; d2 = fmaf(d, d, d2);
            d = qp[ii][5]  - p1.y; d2 = fmaf(d, d, d2);
            d = qp[ii][6]  - p1.z; d2 = fmaf(d, d, d2);
            d = qp[ii][7]  - p1.w; d2 = fmaf(d, d, d2);
            d = qp[ii][8]  - p2.x; d2 = fmaf(d, d, d2);
            d = qp[ii][9]  - p2.y; d2 = fmaf(d, d, d2);
            d = qp[ii][10] - p2.z; d2 = fmaf(d, d, d2);
            d = qp[ii][11] - p2.w; d2 = fmaf(d, d, d2);

            float bias = g_bias[((size_t)h * Nn + i0 + ii) * Nn + j];
            float mi = ii ? mi1 : mi0;
            float lg = qk * s1 + bias - 0.5f * hwv * d2 + INFV * (mi * mj - 1.f);
            if (ii == 0) { row0[j] = lg; mx0 = fmaxf(mx0, lg); }
            else         { row1[j] = lg; mx1 = fmaxf(mx1, lg); }
        }
    }

    #pragma unroll
    for (int off = 16; off; off >>= 1) {
        mx0 = fmaxf(mx0, __shfl_xor_sync(0xffffffffu, mx0, off));
        mx1 = fmaxf(mx1, __shfl_xor_sync(0xffffffffu, mx1, off));
    }
    float s0 = 0.f, sum1 = 0.f;
    for (int jj = lane; jj < Nn; jj += 32) {
        float e0 = __expf(row0[jj] - mx0); row0[jj] = e0; s0   += e0;
        float e1 = __expf(row1[jj] - mx1); row1[jj] = e1; sum1 += e1;
    }
    #pragma unroll
    for (int off = 16; off; off >>= 1) {
        s0   += __shfl_xor_sync(0xffffffffu, s0,   off);
        sum1 += __shfl_xor_sync(0xffffffffu, sum1, off);
    }
    float inv0 = 1.0f / s0, inv1 = 1.0f / sum1;
    float* a0 = g_a + ((size_t)h * Nn + i0) * Nn;
    float* a1 = a0 + Nn;
    for (int jj = lane; jj < Nn; jj += 32) {
        a0[jj] = row0[jj] * inv0;
        a1[jj] = row1[jj] * inv1;
    }
}

// ---------------- KC: o_pair v2 — CTA=i, warp=4 j-rows, all 12 heads ------------
#define SMC_BYTES (21248 * 4)
__global__ __launch_bounds__(256) void opair(const float* __restrict__ z) {
    extern __shared__ float smc[];
    float* zb   = smc;           // [2][32 j][128 ch]
    float* sab  = smc + 8192;    // [2][12 h][32 j]
    float* pred = smc + 8960;    // [8 w][12 h][128 ch]
    const int i = blockIdx.x;
    const int t = threadIdx.x, w = t >> 5, lane = t & 31;

    unsigned long long acc[12][2] = {};

    #pragma unroll
    for (int p = 0; p < 2; p++) {
        float* zdst = zb + p * 4096;
        float* adst = sab + p * 384;
        const float4* zsrc = (const float4*)z + ((size_t)i * Nn + p * 32) * 32;
        #pragma unroll
        for (int k = 0; k < 4; k++) {
            int idx = t + k * 256;
            cp16(smaddr(zdst + (size_t)idx * 4), zsrc + idx);
        }
        if (t < 96) {
            int hh = t >> 3, c = t & 7;
            cp16(smaddr(adst + (size_t)t * 4),
                 (const float4*)(g_a + ((size_t)hh * Nn + i) * Nn + p * 32) + c);
        }
        cp_commit();
    }

    for (int tt = 0; tt < 24; tt++) {
        if (tt < 23) cp_wait<1>(); else cp_wait<0>();
        __syncthreads();

        const float* sz = zb + (tt & 1) * 4096;
        const float* sa = sab + (tt & 1) * 384;
        const int jw = w * 4;

        float4 av[12];
        #pragma unroll
        for (int h = 0; h < 12; h++)
            av[h] = *(const float4*)(sa + h * 32 + jw);
        ulonglong2 zz[4];
        #pragma unroll
        for (int jj = 0; jj < 4; jj++)
            zz[jj] = *(const ulonglong2*)(sz + (jw + jj) * 128 + lane * 4);

        #pragma unroll
        for (int h = 0; h < 12; h++) {
            float a4[4] = {av[h].x, av[h].y, av[h].z, av[h].w};
            #pragma unroll
            for (int jj = 0; jj < 4; jj++) {
                F2U u; u.f.x = a4[jj]; u.f.y = a4[jj];
                ffma2(acc[h][0], u.u, zz[jj].x);
                ffma2(acc[h][1], u.u, zz[jj].y);
            }
        }
        __syncthreads();

        if (tt + 2 < 24) {
            float* zdst = zb + (tt & 1) * 4096;
            float* adst = sab + (tt & 1) * 384;
            const float4* zsrc = (const float4*)z + ((size_t)i * Nn + (tt + 2) * 32) * 32;
            #pragma unroll
            for (int k = 0; k < 4; k++) {
                int idx = t + k * 256;
                cp16(smaddr(zdst + (size_t)idx * 4), zsrc + idx);
            }
            if (t < 96) {
                int hh = t >> 3, c = t & 7;
                cp16(smaddr(adst + (size_t)t * 4),
                     (const float4*)(g_a + ((size_t)hh * Nn + i) * Nn + (tt + 2) * 32) + c);
            }
            cp_commit();
        }
    }

    #pragma unroll
    for (int h = 0; h < 12; h++) {
        F2U lo, hi; lo.u = acc[h][0]; hi.u = acc[h][1];
        float4 v = {lo.f.x, lo.f.y, hi.f.x, hi.f.y};
        *(float4*)(pred + (w * 12 + h) * 128 + lane * 4) = v;
    }
    __syncthreads();
    float* crow = g_cat + (size_t)i * DOUT + 576;
    for (int r = t; r < 1536; r += 256) {
        float s2 = 0.f;
        #pragma unroll
        for (int wp = 0; wp < 8; wp++) s2 += pred[wp * 1536 + r];
        crow[r] = s2;
    }
}

// ---------------- KD: o + o_pt, packed f32x2 accumulation; 2 i's per CTA --------
__global__ __launch_bounds__(384) void attn_out(const float* __restrict__ rot,
                                                const float* __restrict__ trans) {
    int i0 = blockIdx.x * 2;
    int h = threadIdx.x >> 5, lane = threadIdx.x & 31;

    unsigned long long aou[2][8] = {};
    unsigned long long apu[2][12] = {};

    for (int j0 = 0; j0 < Nn; j0 += 32) {
        int j = j0 + lane;
        const ulonglong2* vb = (const ulonglong2*)(g_vh + ((size_t)h * Nn + j) * 16);
        ulonglong2 v0 = vb[0], v1 = vb[1], v2 = vb[2], v3 = vb[3];
        const ulonglong2* pb = (const ulonglong2*)(g_vph + ((size_t)h * Nn + j) * 24);
        ulonglong2 p0 = pb[0], p1 = pb[1], p2 = pb[2], p3 = pb[3], p4 = pb[4], p5 = pb[5];

        #pragma unroll
        for (int ii = 0; ii < 2; ii++) {
            float a = g_a[((size_t)h * Nn + i0 + ii) * Nn + j];
            F2U au; au.f.x = a; au.f.y = a;
            ffma2(aou[ii][0], au.u, v0.x); ffma2(aou[ii][1], au.u, v0.y);
            ffma2(aou[ii][2], au.u, v1.x); ffma2(aou[ii][3], au.u, v1.y);
            ffma2(aou[ii][4], au.u, v2.x); ffma2(aou[ii][5], au.u, v2.y);
            ffma2(aou[ii][6], au.u, v3.x); ffma2(aou[ii][7], au.u, v3.y);

            ffma2(apu[ii][0],  au.u, p0.x); ffma2(apu[ii][1],  au.u, p0.y);
            ffma2(apu[ii][2],  au.u, p1.x); ffma2(apu[ii][3],  au.u, p1.y);
            ffma2(apu[ii][4],  au.u, p2.x); ffma2(apu[ii][5],  au.u, p2.y);
            ffma2(apu[ii][6],  au.u, p3.x); ffma2(apu[ii][7],  au.u, p3.y);
            ffma2(apu[ii][8],  au.u, p4.x); ffma2(apu[ii][9],  au.u, p4.y);
            ffma2(apu[ii][10], au.u, p5.x); ffma2(apu[ii][11], au.u, p5.y);
        }
    }

    #pragma unroll
    for (int off = 16; off; off >>= 1) {
        #pragma unroll
        for (int ii = 0; ii < 2; ii++) {
            #pragma unroll
            for (int k = 0; k < 8; k++)
                addf2(aou[ii][k], __shfl_xor_sync(0xffffffffu, aou[ii][k], off));
            #pragma unroll
            for (int k = 0; k < 12; k++)
                addf2(apu[ii][k], __shfl_xor_sync(0xffffffffu, apu[ii][k], off));
        }
    }

    if (lane == 0) {
        #pragma unroll
        for (int ii = 0; ii < 2; ii++) {
            int i = i0 + ii;
            float* crow = g_cat + (size_t)i * DOUT;
            #pragma unroll
            for (int k = 0; k < 8; k++) {
                F2U u; u.u = aou[ii][k];
                crow[h * 16 + 2*k]     = u.f.x;
                crow[h * 16 + 2*k + 1] = u.f.y;
            }
            float ap[24];
            #pragma unroll
            for (int k = 0; k < 12; k++) {
                F2U u; u.u = apu[ii][k];
                ap[2*k] = u.f.x; ap[2*k+1] = u.f.y;
            }
            float R[9];
            #pragma unroll
            for (int e = 0; e < 9; e++) R[e] = rot[i * 9 + e];
            float t0 = trans[i*3+0], t1 = trans[i*3+1], t2 = trans[i*3+2];
            #pragma unroll
            for (int p = 0; p < 8; p++) {
                float dx = ap[p*3+0] - t0;
                float dy = ap[p*3+1] - t1;
                float dz = ap[p*3+2] - t2;
                float lx = R[0]*dx + R[3]*dy + R[6]*dz;
                float ly = R[1]*dx + R[4]*dy + R[7]*dz;
                float lz = R[2]*dx + R[5]*dy + R[8]*dz;
                crow[192 + (h*8+p)*3 + 0] = lx;
                crow[192 + (h*8+p)*3 + 1] = ly;
                crow[192 + (h*8+p)*3 + 2] = lz;
                crow[480 + h*8 + p] = sqrtf(lx*lx + ly*ly + lz*lz + 1e-8f);
            }
        }
    }
}

// ---------------- host ----------------
extern "C" void kernel_launch(void* const* d_in, const int* in_sizes, int n_in,
                              void* d_out, int out_size) {
    const float* s      = (const float*)d_in[0];
    const float* z      = (const float*)d_in[1];
    const float* rot    = (const float*)d_in[2];
    const float* trans  = (const float*)d_in[3];
    const float* mask   = (const float*)d_in[4];
    const float* w_q    = (const float*)d_in[5];
    const float* b_q    = (const float*)d_in[6];
    const float* w_kv   = (const float*)d_in[7];
    const float* b_kv   = (const float*)d_in[8];
    const float* w_qp   = (const float*)d_in[9];
    const float* b_qp   = (const float*)d_in[10];
    const float* w_kvp  = (const float*)d_in[11];
    const float* b_kvp  = (const float*)d_in[12];
    const float* w_b    = (const float*)d_in[13];
    const float* b_b    = (const float*)d_in[14];
    const float* hw     = (const float*)d_in[15];
    const float* w_out  = (const float*)d_in[16];
    const float* b_out  = (const float*)d_in[17];
    float* out = (float*)d_out;

    cudaFuncSetAttribute(fusedA1, cudaFuncAttributeMaxDynamicSharedMemorySize, SMA_BYTES);
    cudaFuncSetAttribute(fusedA2, cudaFuncAttributeMaxDynamicSharedMemorySize, SMA_BYTES);
    cudaFuncSetAttribute(fusedA3, cudaFuncAttributeMaxDynamicSharedMemorySize, SMA_BYTES);
    cudaFuncSetAttribute(attn_logits2, cudaFuncAttributeMaxDynamicSharedMemorySize, SMB_BYTES);
    cudaFuncSetAttribute(opair,        cudaFuncAttributeMaxDynamicSharedMemorySize, SMC_BYTES);

    fusedA1<<<256 + 1728, 256, SMA_BYTES>>>(z, w_b, b_b, w_q, b_q, w_kv, b_kv,
                                            w_qp, b_qp, w_kvp, b_kvp);
    fusedA2<<<256 + 216, 256, SMA_BYTES>>>(z, w_b, b_b, s);
    fusedA3<<<256 + 768, 256, SMA_BYTES>>>(z, w_b, b_b, rot, trans);
    attn_logits2<<<Nn / 2, 384, SMB_BYTES>>>(mask, hw);
    opair<<<Nn, 256, SMC_BYTES>>>(z);
    attn_out<<<Nn / 2, 384>>>(rot, trans);
    gemm_out_split<<<dim3(CSd / 64, Nn / 64, 3), 256>>>(w_out);
    gemm_out_combine<<<(Nn * CSd + 255) / 256, 256>>>(b_out, out);
}

// round 16
// speedup vs baseline: 1.0364x; 1.0364x over previous
#include <cuda_runtime.h>
#include <cstdint>
#include <cmath>

#define Nn    768
#define CSd   384
#define NPROJ 1152
#define DOUT  2112
#define INFV  100000.0f

__device__ float g_proj [Nn * NPROJ];
__device__ float g_wcat [NPROJ * CSd];
__device__ float g_bcat [NPROJ];
__device__ float g_kh  [12 * Nn * 16];
__device__ float g_vh  [12 * Nn * 16];
__device__ float g_kph [12 * Nn * 12];
__device__ float g_vph [12 * Nn * 24];
__device__ float g_qpts[Nn * 144];
__device__ float g_bias[(size_t)12 * Nn * Nn];
__device__ float g_a   [(size_t)12 * Nn * Nn];
__device__ float g_cat [Nn * DOUT];
__device__ float g_part[3 * Nn * CSd];

__device__ __forceinline__ void ffma2(unsigned long long& d,
                                      unsigned long long a,
                                      unsigned long long b) {
    asm("fma.rn.f32x2 %0, %1, %2, %0;" : "+l"(d) : "l"(a), "l"(b));
}
__device__ __forceinline__ void addf2(unsigned long long& d, unsigned long long a) {
    asm("add.rn.f32x2 %0, %0, %1;" : "+l"(d) : "l"(a));
}
union F2U { unsigned long long u; float2 f; };

__device__ __forceinline__ uint32_t smaddr(const void* p) {
    return (uint32_t)__cvta_generic_to_shared(p);
}
__device__ __forceinline__ void cp16(uint32_t dst, const void* src) {
    asm volatile("cp.async.cg.shared.global [%0], [%1], 16;" :: "r"(dst), "l"(src));
}
__device__ __forceinline__ void cp_commit() {
    asm volatile("cp.async.commit_group;");
}
template<int N> __device__ __forceinline__ void cp_wait() {
    asm volatile("cp.async.wait_group %0;" :: "n"(N));
}

// ---------------- K0a: concat projection weights ----------------
__global__ void copy_weights(const float* __restrict__ wq,  const float* __restrict__ bq,
                             const float* __restrict__ wkv, const float* __restrict__ bkv,
                             const float* __restrict__ wqp, const float* __restrict__ bqp,
                             const float* __restrict__ wkvp,const float* __restrict__ bkvp) {
    int idx = blockIdx.x * 256 + threadIdx.x;
    if (idx < NPROJ * CSd) {
        int r = idx / CSd, k = idx - r * CSd;
        float v;
        if      (r < 192) v = wq  [ r        * CSd + k];
        else if (r < 576) v = wkv [(r - 192) * CSd + k];
        else if (r < 720) v = wqp [(r - 576) * CSd + k];
        else              v = wkvp[(r - 720) * CSd + k];
        g_wcat[idx] = v;
    }
    if (idx < NPROJ) {
        int r = idx;
        g_bcat[r] = (r < 192) ? bq[r] : (r < 576) ? bkv[r-192]
                  : (r < 720) ? bqp[r-576] : bkvp[r-720];
    }
}

// ---------------- projection GEMM ----------------
__global__ void gemm_proj(const float* __restrict__ A) {
    constexpr int KK = CSd;
    constexpr int NC = NPROJ;
    const float* B    = g_wcat;
    const float* bias = g_bcat;
    float*       C    = g_proj;

    __shared__ float As[64][17];
    __shared__ float Bs[64][17];
    int t  = threadIdx.x;
    int m0 = blockIdx.y * 64, n0 = blockIdx.x * 64;
    int lr = t >> 2, lc = (t & 3) * 4;
    int ty = (t >> 4) * 4, tx = (t & 15) * 4;
    float acc[4][4] = {};

    for (int k0 = 0; k0 < KK; k0 += 16) {
        __syncthreads();
        float4 a4 = *(const float4*)(A + (size_t)(m0 + lr) * KK + k0 + lc);
        float4 b4 = *(const float4*)(B + (size_t)(n0 + lr) * KK + k0 + lc);
        As[lr][lc] = a4.x; As[lr][lc+1] = a4.y; As[lr][lc+2] = a4.z; As[lr][lc+3] = a4.w;
        Bs[lr][lc] = b4.x; Bs[lr][lc+1] = b4.y; Bs[lr][lc+2] = b4.z; Bs[lr][lc+3] = b4.w;
        __syncthreads();
        #pragma unroll
        for (int kk = 0; kk < 16; kk++) {
            float av[4], bv[4];
            #pragma unroll
            for (int r = 0; r < 4; r++) av[r] = As[ty + r][kk];
            #pragma unroll
            for (int c = 0; c < 4; c++) bv[c] = Bs[tx + c][kk];
            #pragma unroll
            for (int r = 0; r < 4; r++)
                #pragma unroll
                for (int c = 0; c < 4; c++)
                    acc[r][c] = fmaf(av[r], bv[c], acc[r][c]);
        }
    }
    #pragma unroll
    for (int r = 0; r < 4; r++)
        #pragma unroll
        for (int c = 0; c < 4; c++)
            C[(size_t)(m0 + ty + r) * NC + n0 + tx + c] = acc[r][c] + bias[n0 + tx + c];
}

// ---------------- output GEMM, K split 3 ----------------
__global__ void gemm_out_split(const float* __restrict__ w_out) {
    constexpr int KCH = DOUT / 3;    // 704
    const float* A = g_cat;
    const float* B = w_out;
    int kc = blockIdx.z;
    float* C = g_part + (size_t)kc * Nn * CSd;

    __shared__ float As[64][17];
    __shared__ float Bs[64][17];
    int t  = threadIdx.x;
    int m0 = blockIdx.y * 64, n0 = blockIdx.x * 64;
    int lr = t >> 2, lc = (t & 3) * 4;
    int ty = (t >> 4) * 4, tx = (t & 15) * 4;
    float acc[4][4] = {};

    for (int k0 = kc * KCH; k0 < (kc + 1) * KCH; k0 += 16) {
        __syncthreads();
        float4 a4 = *(const float4*)(A + (size_t)(m0 + lr) * DOUT + k0 + lc);
        float4 b4 = *(const float4*)(B + (size_t)(n0 + lr) * DOUT + k0 + lc);
        As[lr][lc] = a4.x; As[lr][lc+1] = a4.y; As[lr][lc+2] = a4.z; As[lr][lc+3] = a4.w;
        Bs[lr][lc] = b4.x; Bs[lr][lc+1] = b4.y; Bs[lr][lc+2] = b4.z; Bs[lr][lc+3] = b4.w;
        __syncthreads();
        #pragma unroll
        for (int kk = 0; kk < 16; kk++) {
            float av[4], bv[4];
            #pragma unroll
            for (int r = 0; r < 4; r++) av[r] = As[ty + r][kk];
            #pragma unroll
            for (int c = 0; c < 4; c++) bv[c] = Bs[tx + c][kk];
            #pragma unroll
            for (int r = 0; r < 4; r++)
                #pragma unroll
                for (int c = 0; c < 4; c++)
                    acc[r][c] = fmaf(av[r], bv[c], acc[r][c]);
        }
    }
    #pragma unroll
    for (int r = 0; r < 4; r++)
        #pragma unroll
        for (int c = 0; c < 4; c++)
            C[(size_t)(m0 + ty + r) * CSd + n0 + tx + c] = acc[r][c];
}

__global__ void gemm_out_combine(const float* __restrict__ b_out, float* __restrict__ out) {
    int idx = blockIdx.x * 256 + threadIdx.x;
    if (idx < Nn * CSd) {
        int c = idx % CSd;
        out[idx] = g_part[idx] + g_part[idx + Nn * CSd] + g_part[idx + 2 * Nn * CSd]
                 + b_out[c];
    }
}

// ---------------- K0b: rotate points, repack k/v into [h][j][*] ----------------
__global__ void prep_pts(const float* __restrict__ rot, const float* __restrict__ trans) {
    int n = blockIdx.x;
    const float* pr = g_proj + (size_t)n * NPROJ;
    float R[9];
    #pragma unroll
    for (int e = 0; e < 9; e++) R[e] = rot[n * 9 + e];
    float tr[3] = {trans[n*3+0], trans[n*3+1], trans[n*3+2]};

    for (int t = threadIdx.x; t < 960; t += blockDim.x) {
        if (t < 384) {
            int h = t >> 5, c = t & 31;
            float v = pr[192 + h * 32 + c];
            if (c < 16) g_kh[((size_t)h * Nn + n) * 16 + c]        = v;
            else        g_vh[((size_t)h * Nn + n) * 16 + (c - 16)] = v;
        } else if (t < 528) {
            int e = t - 384;
            int g = e / 3, ax = e - g * 3;
            const float* src = pr + 576 + g * 3;
            g_qpts[n * 144 + e] =
                R[ax*3+0]*src[0] + R[ax*3+1]*src[1] + R[ax*3+2]*src[2] + tr[ax];
        } else {
            int e2 = t - 528;
            int g = e2 / 3, ax = e2 - g * 3;
            const float* src = pr + 720 + g * 3;
            float val = R[ax*3+0]*src[0] + R[ax*3+1]*src[1] + R[ax*3+2]*src[2] + tr[ax];
            int h = g / 12, pp = g - h * 12;
            if (pp < 4) g_kph[((size_t)h * Nn + n) * 12 + pp * 3 + ax]       = val;
            else        g_vph[((size_t)h * Nn + n) * 24 + (pp - 4) * 3 + ax] = val;
        }
    }
}

// ---------------- KA: bias GEMM v3 — 2 rows/thread, cp.async pipeline -----------
#define SMA_BYTES (24080 * 4)
__global__ __launch_bounds__(256) void bias_gemm(const float* __restrict__ z,
                                                 const float* __restrict__ w_b,
                                                 const float* __restrict__ b_b) {
    extern __shared__ float sm[];
    float* swb  = sm + 16384;
    float* sbb  = sm + 17920;
    float* part = sm + 17936;   // [8 cg][12 h][64 j]

    const int i = blockIdx.x;
    const int t = threadIdx.x;
    const int cg = t >> 5, jl = t & 31;

    for (int idx = t; idx < 384; idx += 256)
        ((float4*)swb)[idx] = ((const float4*)w_b)[idx];
    if (t < 12) sbb[t] = b_b[t];

    const float4* zbase = (const float4*)z + (size_t)i * Nn * 32;

    #pragma unroll
    for (int p = 0; p < 2; p++) {
        float* buf = sm + p * 8192;
        const float4* src = zbase + (size_t)p * 64 * 32;
        #pragma unroll
        for (int k = 0; k < 8; k++) {
            int idx = t + k * 256;
            int jj = idx >> 5, c4 = idx & 31;
            cp16(smaddr(buf + (size_t)(jj * 32 + (c4 ^ (jj & 31))) * 4),
                 src + (size_t)jj * 32 + c4);
        }
        cp_commit();
    }

    for (int tt = 0; tt < 12; tt++) {
        if (tt < 11) cp_wait<1>(); else cp_wait<0>();
        __syncthreads();

        const float* zr = sm + (tt & 1) * 8192;
        ulonglong2 zz[2][4];
        #pragma unroll
        for (int e = 0; e < 2; e++) {
            const float* rp = zr + (jl + 32 * e) * 128;
            #pragma unroll
            for (int cc = 0; cc < 4; cc++) {
                int c4 = cg * 4 + cc;
                zz[e][cc] = *(const ulonglong2*)(rp + ((c4 ^ jl) << 2));
            }
        }
        unsigned long long acc[12][2] = {};
        #pragma unroll
        for (int h = 0; h < 12; h++) {
            #pragma unroll
            for (int cc = 0; cc < 4; cc++) {
                int c4 = cg * 4 + cc;
                ulonglong2 ww = *(const ulonglong2*)(swb + h * 128 + (c4 << 2));
                ffma2(acc[h][0], zz[0][cc].x, ww.x);
                ffma2(acc[h][0], zz[0][cc].y, ww.y);
                ffma2(acc[h][1], zz[1][cc].x, ww.x);
                ffma2(acc[h][1], zz[1][cc].y, ww.y);
            }
        }
        #pragma unroll
        for (int h = 0; h < 12; h++) {
            F2U u0; u0.u = acc[h][0];
            F2U u1; u1.u = acc[h][1];
            part[(cg * 12 + h) * 64 + jl]      = u0.f.x + u0.f.y;
            part[(cg * 12 + h) * 64 + jl + 32] = u1.f.x + u1.f.y;
        }
        __syncthreads();

        if (tt + 2 < 12) {
            float* buf = sm + (tt & 1) * 8192;
            const float4* src = zbase + (size_t)(tt + 2) * 64 * 32;
            #pragma unroll
            for (int k = 0; k < 8; k++) {
                int idx = t + k * 256;
                int jj = idx >> 5, c4 = idx & 31;
                cp16(smaddr(buf + (size_t)(jj * 32 + (c4 ^ (jj & 31))) * 4),
                     src + (size_t)jj * 32 + c4);
            }
            cp_commit();
        }

        #pragma unroll
        for (int r = t; r < 768; r += 256) {
            int h = r >> 6, j = r & 63;
            float s2 = 0.f;
            #pragma unroll
            for (int c = 0; c < 8; c++) s2 += part[(c * 12 + h) * 64 + j];
            g_bias[((size_t)h * Nn + i) * Nn + tt * 64 + j] =
                0.5773502691896258f * (s2 + sbb[h]);
        }
    }
}

// ---------------- KB: fused logits + softmax, register-prefetched loads --------
#define SMB_BYTES (12 * 2 * 768 * 4)
__global__ __launch_bounds__(384) void attn_logits2(const float* __restrict__ mask,
                                                    const float* __restrict__ hwraw) {
    extern __shared__ float srows[];
    int i0 = blockIdx.x * 2;
    int h = threadIdx.x >> 5, lane = threadIdx.x & 31;
    float* row0 = srows + (h * 2 + 0) * 768;
    float* row1 = srows + (h * 2 + 1) * 768;

    float q[2][16], qp[2][12];
    #pragma unroll
    for (int ii = 0; ii < 2; ii++) {
        const float4* qs = (const float4*)(g_proj + (size_t)(i0+ii) * NPROJ + h * 16);
        #pragma unroll
        for (int c = 0; c < 4; c++) {
            float4 v = qs[c];
            q[ii][c*4+0] = v.x; q[ii][c*4+1] = v.y; q[ii][c*4+2] = v.z; q[ii][c*4+3] = v.w;
        }
        const float4* ps = (const float4*)(g_qpts + (size_t)(i0+ii) * 144 + h * 12);
        #pragma unroll
        for (int c = 0; c < 3; c++) {
            float4 v = ps[c];
            qp[ii][c*4+0] = v.x; qp[ii][c*4+1] = v.y; qp[ii][c*4+2] = v.z; qp[ii][c*4+3] = v.w;
        }
    }
    float x = hwraw[h];
    float hwv = ((x > 20.f) ? x : log1pf(expf(x))) * 0.13608276348795434f;
    float mi0 = mask[i0], mi1 = mask[i0 + 1];
    const float s1 = 0.14433756729740643f;
    float mx0 = -3.4e38f, mx1 = -3.4e38f;

    const float* bias0 = g_bias + ((size_t)h * Nn + i0) * Nn;
    const float* bias1 = bias0 + Nn;

    // prefetch tile 0
    float4 nk0, nk1, nk2, nk3, np0, np1, np2;
    float nb0, nb1, nmj;
    {
        int j = lane;
        const float4* kb = (const float4*)(g_kh + ((size_t)h * Nn + j) * 16);
        nk0 = kb[0]; nk1 = kb[1]; nk2 = kb[2]; nk3 = kb[3];
        const float4* pb = (const float4*)(g_kph + ((size_t)h * Nn + j) * 12);
        np0 = pb[0]; np1 = pb[1]; np2 = pb[2];
        nb0 = bias0[j]; nb1 = bias1[j]; nmj = mask[j];
    }

    for (int j0 = 0; j0 < Nn; j0 += 32) {
        float4 k0 = nk0, k1 = nk1, k2 = nk2, k3 = nk3;
        float4 p0 = np0, p1 = np1, p2 = np2;
        float b0 = nb0, b1 = nb1, mj = nmj;

        if (j0 + 32 < Nn) {
            int j = j0 + 32 + lane;
            const float4* kb = (const float4*)(g_kh + ((size_t)h * Nn + j) * 16);
            nk0 = kb[0]; nk1 = kb[1]; nk2 = kb[2]; nk3 = kb[3];
            const float4* pb = (const float4*)(g_kph + ((size_t)h * Nn + j) * 12);
            np0 = pb[0]; np1 = pb[1]; np2 = pb[2];
            nb0 = bias0[j]; nb1 = bias1[j]; nmj = mask[j];
        }

        int j = j0 + lane;
        #pragma unroll
        for (int ii = 0; ii < 2; ii++) {
            float qk = 0.f;
            qk = fmaf(q[ii][0],  k0.x, qk); qk = fmaf(q[ii][1],  k0.y, qk);
            qk = fmaf(q[ii][2],  k0.z, qk); qk = fmaf(q[ii][3],  k0.w, qk);
            qk = fmaf(q[ii][4],  k1.x, qk); qk = fmaf(q[ii][5],  k1.y, qk);
            qk = fmaf(q[ii][6],  k1.z, qk); qk = fmaf(q[ii][7],  k1.w, qk);
            qk = fmaf(q[ii][8],  k2.x, qk); qk = fmaf(q[ii][9],  k2.y, qk);
            qk = fmaf(q[ii][10], k2.z, qk); qk = fmaf(q[ii][11], k2.w, qk);
            qk = fmaf(q[ii][12], k3.x, qk); qk = fmaf(q[ii][13], k3.y, qk);
            qk = fmaf(q[ii][14], k3.z, qk); qk = fmaf(q[ii][15], k3.w, qk);

            float d2 = 0.f, d;
            d = qp[ii][0]  - p0.x; d2 = fmaf(d, d, d2);
            d = qp[ii][1]  - p0.y; d2 = fmaf(d, d, d2);
            d = qp[ii][2]  - p0.z; d2 = fmaf(d, d, d2);
            d = qp[ii][3]  - p0.w; d2 = fmaf(d, d, d2);
            d = qp[ii][4]  - p1.x; d2 = fmaf(d, d, d2);
            d = qp[ii][5]  - p1.y; d2 = fmaf(d, d, d2);
            d = qp[ii][6]  - p1.z; d2 = fmaf(d, d, d2);
            d = qp[ii][7]  - p1.w; d2 = fmaf(d, d, d2);
            d = qp[ii][8]  - p2.x; d2 = fmaf(d, d, d2);
            d = qp[ii][9]  - p2.y; d2 = fmaf(d, d, d2);
            d = qp[ii][10] - p2.z; d2 = fmaf(d, d, d2);
            d = qp[ii][11] - p2.w; d2 = fmaf(d, d, d2);

            float bias = ii ? b1 : b0;
            float mi   = ii ? mi1 : mi0;
            float lg = qk * s1 + bias - 0.5f * hwv * d2 + INFV * (mi * mj - 1.f);
            if (ii == 0) { row0[j] = lg; mx0 = fmaxf(mx0, lg); }
            else         { row1[j] = lg; mx1 = fmaxf(mx1, lg); }
        }
    }

    #pragma unroll
    for (int off = 16; off; off >>= 1) {
        mx0 = fmaxf(mx0, __shfl_xor_sync(0xffffffffu, mx0, off));
        mx1 = fmaxf(mx1, __shfl_xor_sync(0xffffffffu, mx1, off));
    }
    float s0 = 0.f, sum1 = 0.f;
    for (int jj = lane; jj < Nn; jj += 32) {
        float e0 = __expf(row0[jj] - mx0); row0[jj] = e0; s0   += e0;
        float e1 = __expf(row1[jj] - mx1); row1[jj] = e1; sum1 += e1;
    }
    #pragma unroll
    for (int off = 16; off; off >>= 1) {
        s0   += __shfl_xor_sync(0xffffffffu, s0,   off);
        sum1 += __shfl_xor_sync(0xffffffffu, sum1, off);
    }
    float inv0 = 1.0f / s0, inv1 = 1.0f / sum1;
    float* a0 = g_a + ((size_t)h * Nn + i0) * Nn;
    float* a1 = a0 + Nn;
    for (int jj = lane; jj < Nn; jj += 32) {
        a0[jj] = row0[jj] * inv0;
        a1[jj] = row1[jj] * inv1;
    }
}

// ---------------- KC: o_pair v2 — CTA=i, warp=4 j-rows, all 12 heads ------------
#define SMC_BYTES (21248 * 4)
__global__ __launch_bounds__(256) void opair(const float* __restrict__ z) {
    extern __shared__ float smc[];
    float* zb   = smc;           // [2][32 j][128 ch]
    float* sab  = smc + 8192;    // [2][12 h][32 j]
    float* pred = smc + 8960;    // [8 w][12 h][128 ch]
    const int i = blockIdx.x;
    const int t = threadIdx.x, w = t >> 5, lane = t & 31;

    unsigned long long acc[12][2] = {};

    #pragma unroll
    for (int p = 0; p < 2; p++) {
        float* zdst = zb + p * 4096;
        float* adst = sab + p * 384;
        const float4* zsrc = (const float4*)z + ((size_t)i * Nn + p * 32) * 32;
        #pragma unroll
        for (int k = 0; k < 4; k++) {
            int idx = t + k * 256;
            cp16(smaddr(zdst + (size_t)idx * 4), zsrc + idx);
        }
        if (t < 96) {
            int hh = t >> 3, c = t & 7;
            cp16(smaddr(adst + (size_t)t * 4),
                 (const float4*)(g_a + ((size_t)hh * Nn + i) * Nn + p * 32) + c);
        }
        cp_commit();
    }

    for (int tt = 0; tt < 24; tt++) {
        if (tt < 23) cp_wait<1>(); else cp_wait<0>();
        __syncthreads();

        const float* sz = zb + (tt & 1) * 4096;
        const float* sa = sab + (tt & 1) * 384;
        const int jw = w * 4;

        float4 av[12];
        #pragma unroll
        for (int h = 0; h < 12; h++)
            av[h] = *(const float4*)(sa + h * 32 + jw);
        ulonglong2 zz[4];
        #pragma unroll
        for (int jj = 0; jj < 4; jj++)
            zz[jj] = *(const ulonglong2*)(sz + (jw + jj) * 128 + lane * 4);

        #pragma unroll
        for (int h = 0; h < 12; h++) {
            float a4[4] = {av[h].x, av[h].y, av[h].z, av[h].w};
            #pragma unroll
            for (int jj = 0; jj < 4; jj++) {
                F2U u; u.f.x = a4[jj]; u.f.y = a4[jj];
                ffma2(acc[h][0], u.u, zz[jj].x);
                ffma2(acc[h][1], u.u, zz[jj].y);
            }
        }
        __syncthreads();

        if (tt + 2 < 24) {
            float* zdst = zb + (tt & 1) * 4096;
            float* adst = sab + (tt & 1) * 384;
            const float4* zsrc = (const float4*)z + ((size_t)i * Nn + (tt + 2) * 32) * 32;
            #pragma unroll
            for (int k = 0; k < 4; k++) {
                int idx = t + k * 256;
                cp16(smaddr(zdst + (size_t)idx * 4), zsrc + idx);
            }
            if (t < 96) {
                int hh = t >> 3, c = t & 7;
                cp16(smaddr(adst + (size_t)t * 4),
                     (const float4*)(g_a + ((size_t)hh * Nn + i) * Nn + (tt + 2) * 32) + c);
            }
            cp_commit();
        }
    }

    #pragma unroll
    for (int h = 0; h < 12; h++) {
        F2U lo, hi; lo.u = acc[h][0]; hi.u = acc[h][1];
        float4 v = {lo.f.x, lo.f.y, hi.f.x, hi.f.y};
        *(float4*)(pred + (w * 12 + h) * 128 + lane * 4) = v;
    }
    __syncthreads();
    float* crow = g_cat + (size_t)i * DOUT + 576;
    for (int r = t; r < 1536; r += 256) {
        float s2 = 0.f;
        #pragma unroll
        for (int wp = 0; wp < 8; wp++) s2 += pred[wp * 1536 + r];
        crow[r] = s2;
    }
}

// ---------------- KD: o + o_pt, packed f32x2 accumulation; 2 i's per CTA --------
__global__ __launch_bounds__(384) void attn_out(const float* __restrict__ rot,
                                                const float* __restrict__ trans) {
    int i0 = blockIdx.x * 2;
    int h = threadIdx.x >> 5, lane = threadIdx.x & 31;

    unsigned long long aou[2][8] = {};
    unsigned long long apu[2][12] = {};

    for (int j0 = 0; j0 < Nn; j0 += 32) {
        int j = j0 + lane;
        const ulonglong2* vb = (const ulonglong2*)(g_vh + ((size_t)h * Nn + j) * 16);
        ulonglong2 v0 = vb[0], v1 = vb[1], v2 = vb[2], v3 = vb[3];
        const ulonglong2* pb = (const ulonglong2*)(g_vph + ((size_t)h * Nn + j) * 24);
        ulonglong2 p0 = pb[0], p1 = pb[1], p2 = pb[2], p3 = pb[3], p4 = pb[4], p5 = pb[5];

        #pragma unroll
        for (int ii = 0; ii < 2; ii++) {
            float a = g_a[((size_t)h * Nn + i0 + ii) * Nn + j];
            F2U au; au.f.x = a; au.f.y = a;
            ffma2(aou[ii][0], au.u, v0.x); ffma2(aou[ii][1], au.u, v0.y);
            ffma2(aou[ii][2], au.u, v1.x); ffma2(aou[ii][3], au.u, v1.y);
            ffma2(aou[ii][4], au.u, v2.x); ffma2(aou[ii][5], au.u, v2.y);
            ffma2(aou[ii][6], au.u, v3.x); ffma2(aou[ii][7], au.u, v3.y);

            ffma2(apu[ii][0],  au.u, p0.x); ffma2(apu[ii][1],  au.u, p0.y);
            ffma2(apu[ii][2],  au.u, p1.x); ffma2(apu[ii][3],  au.u, p1.y);
            ffma2(apu[ii][4],  au.u, p2.x); ffma2(apu[ii][5],  au.u, p2.y);
            ffma2(apu[ii][6],  au.u, p3.x); ffma2(apu[ii][7],  au.u, p3.y);
            ffma2(apu[ii][8],  au.u, p4.x); ffma2(apu[ii][9],  au.u, p4.y);
            ffma2(apu[ii][10], au.u, p5.x); ffma2(apu[ii][11], au.u, p5.y);
        }
    }

    #pragma unroll
    for (int off = 16; off; off >>= 1) {
        #pragma unroll
        for (int ii = 0; ii < 2; ii++) {
            #pragma unroll
            for (int k = 0; k < 8; k++)
                addf2(aou[ii][k], __shfl_xor_sync(0xffffffffu, aou[ii][k], off));
            #pragma unroll
            for (int k = 0; k < 12; k++)
                addf2(apu[ii][k], __shfl_xor_sync(0xffffffffu, apu[ii][k], off));
        }
    }

    if (lane == 0) {
        #pragma unroll
        for (int ii = 0; ii < 2; ii++) {
            int i = i0 + ii;
            float* crow = g_cat + (size_t)i * DOUT;
            #pragma unroll
            for (int k = 0; k < 8; k++) {
                F2U u; u.u = aou[ii][k];
                crow[h * 16 + 2*k]     = u.f.x;
                crow[h * 16 + 2*k + 1] = u.f.y;
            }
            float ap[24];
            #pragma unroll
            for (int k = 0; k < 12; k++) {
                F2U u; u.u = apu[ii][k];
                ap[2*k] = u.f.x; ap[2*k+1] = u.f.y;
            }
            float R[9];
            #pragma unroll
            for (int e = 0; e < 9; e++) R[e] = rot[i * 9 + e];
            float t0 = trans[i*3+0], t1 = trans[i*3+1], t2 = trans[i*3+2];
            #pragma unroll
            for (int p = 0; p < 8; p++) {
                float dx = ap[p*3+0] - t0;
                float dy = ap[p*3+1] - t1;
                float dz = ap[p*3+2] - t2;
                float lx = R[0]*dx + R[3]*dy + R[6]*dz;
                float ly = R[1]*dx + R[4]*dy + R[7]*dz;
                float lz = R[2]*dx + R[5]*dy + R[8]*dz;
                crow[192 + (h*8+p)*3 + 0] = lx;
                crow[192 + (h*8+p)*3 + 1] = ly;
                crow[192 + (h*8+p)*3 + 2] = lz;
                crow[480 + h*8 + p] = sqrtf(lx*lx + ly*ly + lz*lz + 1e-8f);
            }
        }
    }
}

// ---------------- host ----------------
extern "C" void kernel_launch(void* const* d_in, const int* in_sizes, int n_in,
                              void* d_out, int out_size) {
    const float* s      = (const float*)d_in[0];
    const float* z      = (const float*)d_in[1];
    const float* rot    = (const float*)d_in[2];
    const float* trans  = (const float*)d_in[3];
    const float* mask   = (const float*)d_in[4];
    const float* w_q    = (const float*)d_in[5];
    const float* b_q    = (const float*)d_in[6];
    const float* w_kv   = (const float*)d_in[7];
    const float* b_kv   = (const float*)d_in[8];
    const float* w_qp   = (const float*)d_in[9];
    const float* b_qp   = (const float*)d_in[10];
    const float* w_kvp  = (const float*)d_in[11];
    const float* b_kvp  = (const float*)d_in[12];
    const float* w_b    = (const float*)d_in[13];
    const float* b_b    = (const float*)d_in[14];
    const float* hw     = (const float*)d_in[15];
    const float* w_out  = (const float*)d_in[16];
    const float* b_out  = (const float*)d_in[17];
    float* out = (float*)d_out;

    cudaFuncSetAttribute(bias_gemm,    cudaFuncAttributeMaxDynamicSharedMemorySize, SMA_BYTES);
    cudaFuncSetAttribute(attn_logits2, cudaFuncAttributeMaxDynamicSharedMemorySize, SMB_BYTES);
    cudaFuncSetAttribute(opair,        cudaFuncAttributeMaxDynamicSharedMemorySize, SMC_BYTES);

    copy_weights<<<(NPROJ * CSd + 255) / 256, 256>>>(w_q, b_q, w_kv, b_kv,
                                                     w_qp, b_qp, w_kvp, b_kvp);
    gemm_proj<<<dim3(NPROJ / 64, Nn / 64), 256>>>(s);
    prep_pts<<<Nn, 128>>>(rot, trans);
    bias_gemm<<<Nn, 256, SMA_BYTES>>>(z, w_b, b_b);
    attn_logits2<<<Nn / 2, 384, SMB_BYTES>>>(mask, hw);
    opair<<<Nn, 256, SMC_BYTES>>>(z);
    attn_out<<<Nn / 2, 384>>>(rot, trans);
    gemm_out_split<<<dim3(CSd / 64, Nn / 64, 3), 256>>>(w_out);
    gemm_out_combine<<<(Nn * CSd + 255) / 256, 256>>>(b_out, out);
}

// round 17
// speedup vs baseline: 1.0515x; 1.0146x over previous
#include <cuda_runtime.h>
#include <cstdint>
#include <cmath>

#define Nn    768
#define CSd   384
#define NPROJ 1152
#define DOUT  2112
#define INFV  100000.0f

__device__ float g_proj [Nn * NPROJ];
__device__ float g_wcat [NPROJ * CSd];
__device__ float g_bcat [NPROJ];
__device__ float g_kh  [12 * Nn * 16];
__device__ float g_vh  [12 * Nn * 16];
__device__ float g_kph [12 * Nn * 12];
__device__ float g_vph [12 * Nn * 24];
__device__ float g_qpts[Nn * 144];
__device__ float g_bias[(size_t)12 * Nn * Nn];
__device__ float g_a   [(size_t)12 * Nn * Nn];
__device__ float g_cat [Nn * DOUT];
__device__ float g_part[3 * Nn * CSd];

__device__ __forceinline__ void ffma2(unsigned long long& d,
                                      unsigned long long a,
                                      unsigned long long b) {
    asm("fma.rn.f32x2 %0, %1, %2, %0;" : "+l"(d) : "l"(a), "l"(b));
}
__device__ __forceinline__ void addf2(unsigned long long& d, unsigned long long a) {
    asm("add.rn.f32x2 %0, %0, %1;" : "+l"(d) : "l"(a));
}
union F2U { unsigned long long u; float2 f; };

__device__ __forceinline__ uint32_t smaddr(const void* p) {
    return (uint32_t)__cvta_generic_to_shared(p);
}
__device__ __forceinline__ void cp16(uint32_t dst, const void* src) {
    asm volatile("cp.async.cg.shared.global [%0], [%1], 16;" :: "r"(dst), "l"(src));
}
__device__ __forceinline__ void cp_commit() {
    asm volatile("cp.async.commit_group;");
}
template<int N> __device__ __forceinline__ void cp_wait() {
    asm volatile("cp.async.wait_group %0;" :: "n"(N));
}

// ---------------- K0a: concat projection weights ----------------
__global__ void copy_weights(const float* __restrict__ wq,  const float* __restrict__ bq,
                             const float* __restrict__ wkv, const float* __restrict__ bkv,
                             const float* __restrict__ wqp, const float* __restrict__ bqp,
                             const float* __restrict__ wkvp,const float* __restrict__ bkvp) {
    int idx = blockIdx.x * 256 + threadIdx.x;
    if (idx < NPROJ * CSd) {
        int r = idx / CSd, k = idx - r * CSd;
        float v;
        if      (r < 192) v = wq  [ r        * CSd + k];
        else if (r < 576) v = wkv [(r - 192) * CSd + k];
        else if (r < 720) v = wqp [(r - 576) * CSd + k];
        else              v = wkvp[(r - 720) * CSd + k];
        g_wcat[idx] = v;
    }
    if (idx < NPROJ) {
        int r = idx;
        g_bcat[r] = (r < 192) ? bq[r] : (r < 576) ? bkv[r-192]
                  : (r < 720) ? bqp[r-576] : bkvp[r-720];
    }
}

// ---------------- projection GEMM ----------------
__global__ void gemm_proj(const float* __restrict__ A) {
    constexpr int KK = CSd;
    constexpr int NC = NPROJ;
    const float* B    = g_wcat;
    const float* bias = g_bcat;
    float*       C    = g_proj;

    __shared__ float As[64][17];
    __shared__ float Bs[64][17];
    int t  = threadIdx.x;
    int m0 = blockIdx.y * 64, n0 = blockIdx.x * 64;
    int lr = t >> 2, lc = (t & 3) * 4;
    int ty = (t >> 4) * 4, tx = (t & 15) * 4;
    float acc[4][4] = {};

    for (int k0 = 0; k0 < KK; k0 += 16) {
        __syncthreads();
        float4 a4 = *(const float4*)(A + (size_t)(m0 + lr) * KK + k0 + lc);
        float4 b4 = *(const float4*)(B + (size_t)(n0 + lr) * KK + k0 + lc);
        As[lr][lc] = a4.x; As[lr][lc+1] = a4.y; As[lr][lc+2] = a4.z; As[lr][lc+3] = a4.w;
        Bs[lr][lc] = b4.x; Bs[lr][lc+1] = b4.y; Bs[lr][lc+2] = b4.z; Bs[lr][lc+3] = b4.w;
        __syncthreads();
        #pragma unroll
        for (int kk = 0; kk < 16; kk++) {
            float av[4], bv[4];
            #pragma unroll
            for (int r = 0; r < 4; r++) av[r] = As[ty + r][kk];
            #pragma unroll
            for (int c = 0; c < 4; c++) bv[c] = Bs[tx + c][kk];
            #pragma unroll
            for (int r = 0; r < 4; r++)
                #pragma unroll
                for (int c = 0; c < 4; c++)
                    acc[r][c] = fmaf(av[r], bv[c], acc[r][c]);
        }
    }
    #pragma unroll
    for (int r = 0; r < 4; r++)
        #pragma unroll
        for (int c = 0; c < 4; c++)
            C[(size_t)(m0 + ty + r) * NC + n0 + tx + c] = acc[r][c] + bias[n0 + tx + c];
}

// ---------------- output GEMM, K split 3 ----------------
__global__ void gemm_out_split(const float* __restrict__ w_out) {
    constexpr int KCH = DOUT / 3;    // 704
    const float* A = g_cat;
    const float* B = w_out;
    int kc = blockIdx.z;
    float* C = g_part + (size_t)kc * Nn * CSd;

    __shared__ float As[64][17];
    __shared__ float Bs[64][17];
    int t  = threadIdx.x;
    int m0 = blockIdx.y * 64, n0 = blockIdx.x * 64;
    int lr = t >> 2, lc = (t & 3) * 4;
    int ty = (t >> 4) * 4, tx = (t & 15) * 4;
    float acc[4][4] = {};

    for (int k0 = kc * KCH; k0 < (kc + 1) * KCH; k0 += 16) {
        __syncthreads();
        float4 a4 = *(const float4*)(A + (size_t)(m0 + lr) * DOUT + k0 + lc);
        float4 b4 = *(const float4*)(B + (size_t)(n0 + lr) * DOUT + k0 + lc);
        As[lr][lc] = a4.x; As[lr][lc+1] = a4.y; As[lr][lc+2] = a4.z; As[lr][lc+3] = a4.w;
        Bs[lr][lc] = b4.x; Bs[lr][lc+1] = b4.y; Bs[lr][lc+2] = b4.z; Bs[lr][lc+3] = b4.w;
        __syncthreads();
        #pragma unroll
        for (int kk = 0; kk < 16; kk++) {
            float av[4], bv[4];
            #pragma unroll
            for (int r = 0; r < 4; r++) av[r] = As[ty + r][kk];
            #pragma unroll
            for (int c = 0; c < 4; c++) bv[c] = Bs[tx + c][kk];
            #pragma unroll
            for (int r = 0; r < 4; r++)
                #pragma unroll
                for (int c = 0; c < 4; c++)
                    acc[r][c] = fmaf(av[r], bv[c], acc[r][c]);
        }
    }
    #pragma unroll
    for (int r = 0; r < 4; r++)
        #pragma unroll
        for (int c = 0; c < 4; c++)
            C[(size_t)(m0 + ty + r) * CSd + n0 + tx + c] = acc[r][c];
}

__global__ void gemm_out_combine(const float* __restrict__ b_out, float* __restrict__ out) {
    int idx = blockIdx.x * 256 + threadIdx.x;
    if (idx < Nn * CSd) {
        int c = idx % CSd;
        out[idx] = g_part[idx] + g_part[idx + Nn * CSd] + g_part[idx + 2 * Nn * CSd]
                 + b_out[c];
    }
}

// ---------------- K0b: rotate points, repack k/v into [h][j][*] ----------------
__global__ void prep_pts(const float* __restrict__ rot, const float* __restrict__ trans) {
    int n = blockIdx.x;
    const float* pr = g_proj + (size_t)n * NPROJ;
    float R[9];
    #pragma unroll
    for (int e = 0; e < 9; e++) R[e] = rot[n * 9 + e];
    float tr[3] = {trans[n*3+0], trans[n*3+1], trans[n*3+2]};

    for (int t = threadIdx.x; t < 960; t += blockDim.x) {
        if (t < 384) {
            int h = t >> 5, c = t & 31;
            float v = pr[192 + h * 32 + c];
            if (c < 16) g_kh[((size_t)h * Nn + n) * 16 + c]        = v;
            else        g_vh[((size_t)h * Nn + n) * 16 + (c - 16)] = v;
        } else if (t < 528) {
            int e = t - 384;
            int g = e / 3, ax = e - g * 3;
            const float* src = pr + 576 + g * 3;
            g_qpts[n * 144 + e] =
                R[ax*3+0]*src[0] + R[ax*3+1]*src[1] + R[ax*3+2]*src[2] + tr[ax];
        } else {
            int e2 = t - 528;
            int g = e2 / 3, ax = e2 - g * 3;
            const float* src = pr + 720 + g * 3;
            float val = R[ax*3+0]*src[0] + R[ax*3+1]*src[1] + R[ax*3+2]*src[2] + tr[ax];
            int h = g / 12, pp = g - h * 12;
            if (pp < 4) g_kph[((size_t)h * Nn + n) * 12 + pp * 3 + ax]       = val;
            else        g_vph[((size_t)h * Nn + n) * 24 + (pp - 4) * 3 + ax] = val;
        }
    }
}

// ---------------- KA: bias GEMM v4 — 32-row tiles, 2-stage, 4 CTAs/SM ------------
// smem floats: zb[2][4096] | swb 1536 | sbb 16 | part [8][12][32]=3072  = 12816
#define SMA_BYTES (12816 * 4)
__global__ __launch_bounds__(256) void bias_gemm(const float* __restrict__ z,
                                                 const float* __restrict__ w_b,
                                                 const float* __restrict__ b_b) {
    extern __shared__ float sm[];
    float* swb  = sm + 8192;
    float* sbb  = sm + 9728;
    float* part = sm + 9744;

    const int i = blockIdx.x;
    const int t = threadIdx.x;
    const int cg = t >> 5, jl = t & 31;

    for (int idx = t; idx < 384; idx += 256)
        ((float4*)swb)[idx] = ((const float4*)w_b)[idx];
    if (t < 12) sbb[t] = b_b[t];

    const float4* zbase = (const float4*)z + (size_t)i * Nn * 32;

    #pragma unroll
    for (int p = 0; p < 2; p++) {
        float* buf = sm + p * 4096;
        const float4* src = zbase + (size_t)p * 32 * 32;
        #pragma unroll
        for (int k = 0; k < 4; k++) {
            int idx = t + k * 256;
            int jj = idx >> 5, c4 = idx & 31;
            cp16(smaddr(buf + (size_t)(jj * 32 + (c4 ^ jj)) * 4),
                 src + (size_t)jj * 32 + c4);
        }
        cp_commit();
    }

    for (int tt = 0; tt < 24; tt++) {
        if (tt < 23) cp_wait<1>(); else cp_wait<0>();
        __syncthreads();

        const float* rp = sm + (tt & 1) * 4096 + jl * 128;
        ulonglong2 zz[4];
        #pragma unroll
        for (int cc = 0; cc < 4; cc++) {
            int c4 = cg * 4 + cc;
            zz[cc] = *(const ulonglong2*)(rp + ((c4 ^ jl) << 2));
        }
        unsigned long long acc[12] = {};
        #pragma unroll
        for (int h = 0; h < 12; h++) {
            #pragma unroll
            for (int cc = 0; cc < 4; cc++) {
                int c4 = cg * 4 + cc;
                ulonglong2 ww = *(const ulonglong2*)(swb + h * 128 + (c4 << 2));
                ffma2(acc[h], zz[cc].x, ww.x);
                ffma2(acc[h], zz[cc].y, ww.y);
            }
        }
        #pragma unroll
        for (int h = 0; h < 12; h++) {
            F2U u; u.u = acc[h];
            part[(cg * 12 + h) * 32 + jl] = u.f.x + u.f.y;
        }
        __syncthreads();

        if (tt + 2 < 24) {
            float* buf = sm + (tt & 1) * 4096;
            const float4* src = zbase + (size_t)(tt + 2) * 32 * 32;
            #pragma unroll
            for (int k = 0; k < 4; k++) {
                int idx = t + k * 256;
                int jj = idx >> 5, c4 = idx & 31;
                cp16(smaddr(buf + (size_t)(jj * 32 + (c4 ^ jj)) * 4),
                     src + (size_t)jj * 32 + c4);
            }
            cp_commit();
        }

        for (int r = t; r < 384; r += 256) {
            int h = r >> 5, j = r & 31;
            float s2 = 0.f;
            #pragma unroll
            for (int c = 0; c < 8; c++) s2 += part[(c * 12 + h) * 32 + j];
            g_bias[((size_t)h * Nn + i) * Nn + tt * 32 + j] =
                0.5773502691896258f * (s2 + sbb[h]);
        }
    }
}

// ---------------- KB: fused logits + softmax, register-prefetched loads --------
#define SMB_BYTES (12 * 2 * 768 * 4)
__global__ __launch_bounds__(384) void attn_logits2(const float* __restrict__ mask,
                                                    const float* __restrict__ hwraw) {
    extern __shared__ float srows[];
    int i0 = blockIdx.x * 2;
    int h = threadIdx.x >> 5, lane = threadIdx.x & 31;
    float* row0 = srows + (h * 2 + 0) * 768;
    float* row1 = srows + (h * 2 + 1) * 768;

    float q[2][16], qp[2][12];
    #pragma unroll
    for (int ii = 0; ii < 2; ii++) {
        const float4* qs = (const float4*)(g_proj + (size_t)(i0+ii) * NPROJ + h * 16);
        #pragma unroll
        for (int c = 0; c < 4; c++) {
            float4 v = qs[c];
            q[ii][c*4+0] = v.x; q[ii][c*4+1] = v.y; q[ii][c*4+2] = v.z; q[ii][c*4+3] = v.w;
        }
        const float4* ps = (const float4*)(g_qpts + (size_t)(i0+ii) * 144 + h * 12);
        #pragma unroll
        for (int c = 0; c < 3; c++) {
            float4 v = ps[c];
            qp[ii][c*4+0] = v.x; qp[ii][c*4+1] = v.y; qp[ii][c*4+2] = v.z; qp[ii][c*4+3] = v.w;
        }
    }
    float x = hwraw[h];
    float hwv = ((x > 20.f) ? x : log1pf(expf(x))) * 0.13608276348795434f;
    float mi0 = mask[i0], mi1 = mask[i0 + 1];
    const float s1 = 0.14433756729740643f;
    float mx0 = -3.4e38f, mx1 = -3.4e38f;

    const float* bias0 = g_bias + ((size_t)h * Nn + i0) * Nn;
    const float* bias1 = bias0 + Nn;

    float4 nk0, nk1, nk2, nk3, np0, np1, np2;
    float nb0, nb1, nmj;
    {
        int j = lane;
        const float4* kb = (const float4*)(g_kh + ((size_t)h * Nn + j) * 16);
        nk0 = kb[0]; nk1 = kb[1]; nk2 = kb[2]; nk3 = kb[3];
        const float4* pb = (const float4*)(g_kph + ((size_t)h * Nn + j) * 12);
        np0 = pb[0]; np1 = pb[1]; np2 = pb[2];
        nb0 = bias0[j]; nb1 = bias1[j]; nmj = mask[j];
    }

    for (int j0 = 0; j0 < Nn; j0 += 32) {
        float4 k0 = nk0, k1 = nk1, k2 = nk2, k3 = nk3;
        float4 p0 = np0, p1 = np1, p2 = np2;
        float b0 = nb0, b1 = nb1, mj = nmj;

        if (j0 + 32 < Nn) {
            int j = j0 + 32 + lane;
            const float4* kb = (const float4*)(g_kh + ((size_t)h * Nn + j) * 16);
            nk0 = kb[0]; nk1 = kb[1]; nk2 = kb[2]; nk3 = kb[3];
            const float4* pb = (const float4*)(g_kph + ((size_t)h * Nn + j) * 12);
            np0 = pb[0]; np1 = pb[1]; np2 = pb[2];
            nb0 = bias0[j]; nb1 = bias1[j]; nmj = mask[j];
        }

        int j = j0 + lane;
        #pragma unroll
        for (int ii = 0; ii < 2; ii++) {
            float qk = 0.f;
            qk = fmaf(q[ii][0],  k0.x, qk); qk = fmaf(q[ii][1],  k0.y, qk);
            qk = fmaf(q[ii][2],  k0.z, qk); qk = fmaf(q[ii][3],  k0.w, qk);
            qk = fmaf(q[ii][4],  k1.x, qk); qk = fmaf(q[ii][5],  k1.y, qk);
            qk = fmaf(q[ii][6],  k1.z, qk); qk = fmaf(q[ii][7],  k1.w, qk);
            qk = fmaf(q[ii][8],  k2.x, qk); qk = fmaf(q[ii][9],  k2.y, qk);
            qk = fmaf(q[ii][10], k2.z, qk); qk = fmaf(q[ii][11], k2.w, qk);
            qk = fmaf(q[ii][12], k3.x, qk); qk = fmaf(q[ii][13], k3.y, qk);
            qk = fmaf(q[ii][14], k3.z, qk); qk = fmaf(q[ii][15], k3.w, qk);

            float d2 = 0.f, d;
            d = qp[ii][0]  - p0.x; d2 = fmaf(d, d, d2);
            d = qp[ii][1]  - p0.y; d2 = fmaf(d, d, d2);
            d = qp[ii][2]  - p0.z; d2 = fmaf(d, d, d2);
            d = qp[ii][3]  - p0.w; d2 = fmaf(d, d, d2);
            d = qp[ii][4]  - p1.x; d2 = fmaf(d, d, d2);
            d = qp[ii][5]  - p1.y; d2 = fmaf(d, d, d2);
            d = qp[ii][6]  - p1.z; d2 = fmaf(d, d, d2);
            d = qp[ii][7]  - p1.w; d2 = fmaf(d, d, d2);
            d = qp[ii][8]  - p2.x; d2 = fmaf(d, d, d2);
            d = qp[ii][9]  - p2.y; d2 = fmaf(d, d, d2);
            d = qp[ii][10] - p2.z; d2 = fmaf(d, d, d2);
            d = qp[ii][11] - p2.w; d2 = fmaf(d, d, d2);

            float bias = ii ? b1 : b0;
            float mi   = ii ? mi1 : mi0;
            float lg = qk * s1 + bias - 0.5f * hwv * d2 + INFV * (mi * mj - 1.f);
            if (ii == 0) { row0[j] = lg; mx0 = fmaxf(mx0, lg); }
            else         { row1[j] = lg; mx1 = fmaxf(mx1, lg); }
        }
    }

    #pragma unroll
    for (int off = 16; off; off >>= 1) {
        mx0 = fmaxf(mx0, __shfl_xor_sync(0xffffffffu, mx0, off));
        mx1 = fmaxf(mx1, __shfl_xor_sync(0xffffffffu, mx1, off));
    }
    float s0 = 0.f, sum1 = 0.f;
    for (int jj = lane; jj < Nn; jj += 32) {
        float e0 = __expf(row0[jj] - mx0); row0[jj] = e0; s0   += e0;
        float e1 = __expf(row1[jj] - mx1); row1[jj] = e1; sum1 += e1;
    }
    #pragma unroll
    for (int off = 16; off; off >>= 1) {
        s0   += __shfl_xor_sync(0xffffffffu, s0,   off);
        sum1 += __shfl_xor_sync(0xffffffffu, sum1, off);
    }
    float inv0 = 1.0f / s0, inv1 = 1.0f / sum1;
    float* a0 = g_a + ((size_t)h * Nn + i0) * Nn;
    float* a1 = a0 + Nn;
    for (int jj = lane; jj < Nn; jj += 32) {
        a0[jj] = row0[jj] * inv0;
        a1[jj] = row1[jj] * inv1;
    }
}

// ---------------- KC: o_pair v2 — CTA=i, warp=4 j-rows, all 12 heads ------------
#define SMC_BYTES (21248 * 4)
__global__ __launch_bounds__(256) void opair(const float* __restrict__ z) {
    extern __shared__ float smc[];
    float* zb   = smc;           // [2][32 j][128 ch]
    float* sab  = smc + 8192;    // [2][12 h][32 j]
    float* pred = smc + 8960;    // [8 w][12 h][128 ch]
    const int i = blockIdx.x;
    const int t = threadIdx.x, w = t >> 5, lane = t & 31;

    unsigned long long acc[12][2] = {};

    #pragma unroll
    for (int p = 0; p < 2; p++) {
        float* zdst = zb + p * 4096;
        float* adst = sab + p * 384;
        const float4* zsrc = (const float4*)z + ((size_t)i * Nn + p * 32) * 32;
        #pragma unroll
        for (int k = 0; k < 4; k++) {
            int idx = t + k * 256;
            cp16(smaddr(zdst + (size_t)idx * 4), zsrc + idx);
        }
        if (t < 96) {
            int hh = t >> 3, c = t & 7;
            cp16(smaddr(adst + (size_t)t * 4),
                 (const float4*)(g_a + ((size_t)hh * Nn + i) * Nn + p * 32) + c);
        }
        cp_commit();
    }

    for (int tt = 0; tt < 24; tt++) {
        if (tt < 23) cp_wait<1>(); else cp_wait<0>();
        __syncthreads();

        const float* sz = zb + (tt & 1) * 4096;
        const float* sa = sab + (tt & 1) * 384;
        const int jw = w * 4;

        float4 av[12];
        #pragma unroll
        for (int h = 0; h < 12; h++)
            av[h] = *(const float4*)(sa + h * 32 + jw);
        ulonglong2 zz[4];
        #pragma unroll
        for (int jj = 0; jj < 4; jj++)
            zz[jj] = *(const ulonglong2*)(sz + (jw + jj) * 128 + lane * 4);

        #pragma unroll
        for (int h = 0; h < 12; h++) {
            float a4[4] = {av[h].x, av[h].y, av[h].z, av[h].w};
            #pragma unroll
            for (int jj = 0; jj < 4; jj++) {
                F2U u; u.f.x = a4[jj]; u.f.y = a4[jj];
                ffma2(acc[h][0], u.u, zz[jj].x);
                ffma2(acc[h][1], u.u, zz[jj].y);
            }
        }
        __syncthreads();

        if (tt + 2 < 24) {
            float* zdst = zb + (tt & 1) * 4096;
            float* adst = sab + (tt & 1) * 384;
            const float4* zsrc = (const float4*)z + ((size_t)i * Nn + (tt + 2) * 32) * 32;
            #pragma unroll
            for (int k = 0; k < 4; k++) {
                int idx = t + k * 256;
                cp16(smaddr(zdst + (size_t)idx * 4), zsrc + idx);
            }
            if (t < 96) {
                int hh = t >> 3, c = t & 7;
                cp16(smaddr(adst + (size_t)t * 4),
                     (const float4*)(g_a + ((size_t)hh * Nn + i) * Nn + (tt + 2) * 32) + c);
            }
            cp_commit();
        }
    }

    #pragma unroll
    for (int h = 0; h < 12; h++) {
        F2U lo, hi; lo.u = acc[h][0]; hi.u = acc[h][1];
        float4 v = {lo.f.x, lo.f.y, hi.f.x, hi.f.y};
        *(float4*)(pred + (w * 12 + h) * 128 + lane * 4) = v;
    }
    __syncthreads();
    float* crow = g_cat + (size_t)i * DOUT + 576;
    for (int r = t; r < 1536; r += 256) {
        float s2 = 0.f;
        #pragma unroll
        for (int wp = 0; wp < 8; wp++) s2 += pred[wp * 1536 + r];
        crow[r] = s2;
    }
}

// ---------------- KD1: o accumulation, 4 i's per CTA, prefetched --------------
__global__ __launch_bounds__(384) void attn_o() {
    int i0 = blockIdx.x * 4;
    int h = threadIdx.x >> 5, lane = threadIdx.x & 31;

    unsigned long long aou[4][8] = {};
    const float* arow = g_a + ((size_t)h * Nn + i0) * Nn;

    ulonglong2 nv0, nv1, nv2, nv3;
    float na0, na1, na2, na3;
    {
        int j = lane;
        const ulonglong2* vb = (const ulonglong2*)(g_vh + ((size_t)h * Nn + j) * 16);
        nv0 = vb[0]; nv1 = vb[1]; nv2 = vb[2]; nv3 = vb[3];
        na0 = arow[j]; na1 = arow[Nn + j]; na2 = arow[2*Nn + j]; na3 = arow[3*Nn + j];
    }

    for (int j0 = 0; j0 < Nn; j0 += 32) {
        ulonglong2 v0 = nv0, v1 = nv1, v2 = nv2, v3 = nv3;
        float a0 = na0, a1 = na1, a2 = na2, a3 = na3;

        if (j0 + 32 < Nn) {
            int j = j0 + 32 + lane;
            const ulonglong2* vb = (const ulonglong2*)(g_vh + ((size_t)h * Nn + j) * 16);
            nv0 = vb[0]; nv1 = vb[1]; nv2 = vb[2]; nv3 = vb[3];
            na0 = arow[j]; na1 = arow[Nn + j]; na2 = arow[2*Nn + j]; na3 = arow[3*Nn + j];
        }

        float av[4] = {a0, a1, a2, a3};
        #pragma unroll
        for (int ii = 0; ii < 4; ii++) {
            F2U au; au.f.x = av[ii]; au.f.y = av[ii];
            ffma2(aou[ii][0], au.u, v0.x); ffma2(aou[ii][1], au.u, v0.y);
            ffma2(aou[ii][2], au.u, v1.x); ffma2(aou[ii][3], au.u, v1.y);
            ffma2(aou[ii][4], au.u, v2.x); ffma2(aou[ii][5], au.u, v2.y);
            ffma2(aou[ii][6], au.u, v3.x); ffma2(aou[ii][7], au.u, v3.y);
        }
    }

    #pragma unroll
    for (int off = 16; off; off >>= 1)
        #pragma unroll
        for (int ii = 0; ii < 4; ii++)
            #pragma unroll
            for (int k = 0; k < 8; k++)
                addf2(aou[ii][k], __shfl_xor_sync(0xffffffffu, aou[ii][k], off));

    if (lane == 0) {
        #pragma unroll
        for (int ii = 0; ii < 4; ii++) {
            float* crow = g_cat + (size_t)(i0 + ii) * DOUT + h * 16;
            #pragma unroll
            for (int k = 0; k < 8; k++) {
                F2U u; u.u = aou[ii][k];
                crow[2*k] = u.f.x; crow[2*k + 1] = u.f.y;
            }
        }
    }
}

// ---------------- KD2: o_pt + inverse frame + norms, 4 i's per CTA ------------
__global__ __launch_bounds__(384) void attn_opt(const float* __restrict__ rot,
                                                const float* __restrict__ trans) {
    int i0 = blockIdx.x * 4;
    int h = threadIdx.x >> 5, lane = threadIdx.x & 31;

    unsigned long long apu[4][12] = {};
    const float* arow = g_a + ((size_t)h * Nn + i0) * Nn;

    ulonglong2 np[6];
    float na[4];
    {
        int j = lane;
        const ulonglong2* pb = (const ulonglong2*)(g_vph + ((size_t)h * Nn + j) * 24);
        #pragma unroll
        for (int k = 0; k < 6; k++) np[k] = pb[k];
        #pragma unroll
        for (int ii = 0; ii < 4; ii++) na[ii] = arow[ii * Nn + j];
    }

    for (int j0 = 0; j0 < Nn; j0 += 32) {
        ulonglong2 p[6];
        float a[4];
        #pragma unroll
        for (int k = 0; k < 6; k++) p[k] = np[k];
        #pragma unroll
        for (int ii = 0; ii < 4; ii++) a[ii] = na[ii];

        if (j0 + 32 < Nn) {
            int j = j0 + 32 + lane;
            const ulonglong2* pb = (const ulonglong2*)(g_vph + ((size_t)h * Nn + j) * 24);
            #pragma unroll
            for (int k = 0; k < 6; k++) np[k] = pb[k];
            #pragma unroll
            for (int ii = 0; ii < 4; ii++) na[ii] = arow[ii * Nn + j];
        }

        #pragma unroll
        for (int ii = 0; ii < 4; ii++) {
            F2U au; au.f.x = a[ii]; au.f.y = a[ii];
            #pragma unroll
            for (int k = 0; k < 6; k++) {
                ffma2(apu[ii][2*k],     au.u, p[k].x);
                ffma2(apu[ii][2*k + 1], au.u, p[k].y);
            }
        }
    }

    #pragma unroll
    for (int off = 16; off; off >>= 1)
        #pragma unroll
        for (int ii = 0; ii < 4; ii++)
            #pragma unroll
            for (int k = 0; k < 12; k++)
                addf2(apu[ii][k], __shfl_xor_sync(0xffffffffu, apu[ii][k], off));

    if (lane == 0) {
        #pragma unroll
        for (int ii = 0; ii < 4; ii++) {
            int i = i0 + ii;
            float* crow = g_cat + (size_t)i * DOUT;
            float ap[24];
            #pragma unroll
            for (int k = 0; k < 12; k++) {
                F2U u; u.u = apu[ii][k];
                ap[2*k] = u.f.x; ap[2*k+1] = u.f.y;
            }
            float R[9];
            #pragma unroll
            for (int e = 0; e < 9; e++) R[e] = rot[i * 9 + e];
            float t0 = trans[i*3+0], t1 = trans[i*3+1], t2 = trans[i*3+2];
            #pragma unroll
            for (int p = 0; p < 8; p++) {
                float dx = ap[p*3+0] - t0;
                float dy = ap[p*3+1] - t1;
                float dz = ap[p*3+2] - t2;
                float lx = R[0]*dx + R[3]*dy + R[6]*dz;
                float ly = R[1]*dx + R[4]*dy + R[7]*dz;
                float lz = R[2]*dx + R[5]*dy + R[8]*dz;
                crow[192 + (h*8+p)*3 + 0] = lx;
                crow[192 + (h*8+p)*3 + 1] = ly;
                crow[192 + (h*8+p)*3 + 2] = lz;
                crow[480 + h*8 + p] = sqrtf(lx*lx + ly*ly + lz*lz + 1e-8f);
            }
        }
    }
}

// ---------------- host ----------------
extern "C" void kernel_launch(void* const* d_in, const int* in_sizes, int n_in,
                              void* d_out, int out_size) {
    const float* s      = (const float*)d_in[0];
    const float* z      = (const float*)d_in[1];
    const float* rot    = (const float*)d_in[2];
    const float* trans  = (const float*)d_in[3];
    const float* mask   = (const float*)d_in[4];
    const float* w_q    = (const float*)d_in[5];
    const float* b_q    = (const float*)d_in[6];
    const float* w_kv   = (const float*)d_in[7];
    const float* b_kv   = (const float*)d_in[8];
    const float* w_qp   = (const float*)d_in[9];
    const float* b_qp   = (const float*)d_in[10];
    const float* w_kvp  = (const float*)d_in[11];
    const float* b_kvp  = (const float*)d_in[12];
    const float* w_b    = (const float*)d_in[13];
    const float* b_b    = (const float*)d_in[14];
    const float* hw     = (const float*)d_in[15];
    const float* w_out  = (const float*)d_in[16];
    const float* b_out  = (const float*)d_in[17];
    float* out = (float*)d_out;

    cudaFuncSetAttribute(bias_gemm,    cudaFuncAttributeMaxDynamicSharedMemorySize, SMA_BYTES);
    cudaFuncSetAttribute(attn_logits2, cudaFuncAttributeMaxDynamicSharedMemorySize, SMB_BYTES);
    cudaFuncSetAttribute(opair,        cudaFuncAttributeMaxDynamicSharedMemorySize, SMC_BYTES);

    copy_weights<<<(NPROJ * CSd + 255) / 256, 256>>>(w_q, b_q, w_kv, b_kv,
                                                     w_qp, b_qp, w_kvp, b_kvp);
    gemm_proj<<<dim3(NPROJ / 64, Nn / 64), 256>>>(s);
    prep_pts<<<Nn, 128>>>(rot, trans);
    bias_gemm<<<Nn, 256, SMA_BYTES>>>(z, w_b, b_b);
    attn_logits2<<<Nn / 2, 384, SMB_BYTES>>>(mask, hw);
    opair<<<Nn, 256, SMC_BYTES>>>(z);
    attn_o<<<Nn / 4, 384>>>();
    attn_opt<<<Nn / 4, 384>>>(rot, trans);
    gemm_out_split<<<dim3(CSd / 64, Nn / 64, 3), 256>>>(w_out);
    gemm_out_combine<<<(Nn * CSd + 255) / 256, 256>>>(b_out, out);
}